// round 14
// baseline (speedup 1.0000x reference)
#include <cuda_runtime.h>
#include <cuda_fp16.h>
#include <cstdint>

// NaiveFourierKANLayer via mma.sync fp16 m16n8k16 (sm_103 portable HMMA path).
// y[b,j] = sum_{i,k} cos(x[b,i]k)C0[j,i,k] + sin(x[b,i]k)C1[j,i,k] + bias[j]
// GEMM: M=2048(b), N=256(j), K flattened: pos = i*600 + d*300 + (k-1),
// K_total = 153600 = 2400 chunks of 64. NO padding. Split-K into 9 arbitrary
// chunk ranges -> grid (16,9) = 144 CTAs, max 267 stages (was 320).

#define NT     512          // gemm threads (16 warps, 4/SMSP)
#define PTN    256          // helper-kernel threads
#define BMT    128          // CTA M tile
#define ID     256
#define JD     256
#define KG     300
#define SPLITS 9
#define NCHUNK 2400         // 153600 / 64

#define CTRL   1024
#define A_SZ   16384        // 128 rows x 128B  (64 fp16 features per row)
#define B_SZ   32768        // 256 rows x 128B  (64 fp16 coeffs per row)
#define STG    (A_SZ + B_SZ)
#define SMEM_TOTAL (CTRL + 3 * STG)   // 148480

// fp16, SW128-pre-swizzled coeff tiles:
// tile T (=chunk): [256 j rows][8 chunks 16B=8 fp16]; position p = T*64 + c*8 + e.
__device__ __align__(128) uint32_t g_B[(size_t)NCHUNK * JD * 32];   // 78.6 MB

__device__ __forceinline__ uint32_t s2u(const void* p) {
    uint32_t a;
    asm("{ .reg .u64 t; cvta.to.shared.u64 t, %1; cvt.u32.u64 %0, t; }" : "=r"(a) : "l"(p));
    return a;
}
// pack two fp32 -> fp16x2 (lo = first arg, hi = second arg), round-to-nearest
__device__ __forceinline__ uint32_t pack_h2(float lo, float hi) {
    uint32_t r;
    asm("cvt.rn.f16x2.f32 %0, %1, %2;" : "=r"(r) : "f"(hi), "f"(lo));
    return r;
}

#define MBAR_INIT(a, c) asm volatile("mbarrier.init.shared.b64 [%0], %1;" :: "r"(a), "r"(c) : "memory")
#define MBAR_ARRIVE(a)  asm volatile("mbarrier.arrive.shared.b64 _, [%0];" :: "r"(a) : "memory")
#define MBAR_EXPECT_TX(a, b) \
    asm volatile("mbarrier.arrive.expect_tx.shared.b64 _, [%0], %1;" :: "r"(a), "r"(b) : "memory")
#define MBAR_WAIT(a, ph)                                                              \
    asm volatile("{\n\t.reg .pred P;\n\t"                                             \
        "WL_%=:\n\t"                                                                  \
        "mbarrier.try_wait.parity.acquire.cta.shared::cta.b64 P, [%0], %1, 0x989680;\n\t" \
        "@P bra.uni WD_%=;\n\t"                                                       \
        "bra.uni WL_%=;\n\t"                                                          \
        "WD_%=:\n\t}" :: "r"(a), "r"(ph) : "memory")

#define LDSM4(R, addr)                                                                \
    asm volatile("ldmatrix.sync.aligned.m8n8.x4.shared.b16 {%0,%1,%2,%3}, [%4];"      \
        : "=r"((R)[0]), "=r"((R)[1]), "=r"((R)[2]), "=r"((R)[3]) : "r"(addr))

__device__ __forceinline__ void mma16(float* d, const uint32_t* a, const uint32_t* b) {
    asm volatile("mma.sync.aligned.m16n8k16.row.col.f32.f16.f16.f32 "
        "{%0,%1,%2,%3}, {%4,%5,%6,%7}, {%8,%9}, {%0,%1,%2,%3};"
        : "+f"(d[0]), "+f"(d[1]), "+f"(d[2]), "+f"(d[3])
        : "r"(a[0]), "r"(a[1]), "r"(a[2]), "r"(a[3]), "r"(b[0]), "r"(b[1]));
}

// ---------------------------------------------------------------------------
__global__ void __launch_bounds__(PTN)
fkan_init(float* __restrict__ out, const float* __restrict__ bias, int n) {
    int t = blockIdx.x * blockDim.x + threadIdx.x;
    if (t < n) out[t] = bias[t & (JD - 1)];
}

// coeffs[d][j][i][k] -> g_B fp16 tiles via the flattened-position map.
// One thread per 16B chunk (8 consecutive positions).
__global__ void __launch_bounds__(PTN)
fkan_pre(const float* __restrict__ co) {
    size_t lin = (size_t)blockIdx.x * PTN + threadIdx.x;   // (T*256+j)*8+c
    if (lin >= (size_t)NCHUNK * JD * 8) return;
    int c = (int)(lin & 7);
    int j = (int)((lin >> 3) & 255);
    int T = (int)(lin >> 11);

    float v[8];
    #pragma unroll
    for (int e = 0; e < 8; e++) {
        int p  = T * 64 + c * 8 + e;
        int i  = p / 600;
        int r6 = p - i * 600;
        int d  = (r6 >= KG) ? 1 : 0;
        int k  = r6 - d * KG;                    // 0-based k index
        v[e] = co[((size_t)(d * JD + j) * ID + i) * KG + k];
    }
    uint4 w;
    w.x = pack_h2(v[0], v[1]); w.y = pack_h2(v[2], v[3]);
    w.z = pack_h2(v[4], v[5]); w.w = pack_h2(v[6], v[7]);
    uint32_t off = (uint32_t)j * 32 + (((uint32_t)c ^ (uint32_t)(j & 7)) << 2); // u32 units
    *(uint4*)(g_B + (size_t)T * 8192 + off) = w;
}

// ---------------------------------------------------------------------------
// Generate run of angles val(n) = trig(xv * (k0 + n)) for n in [a, b), written
// to v[a..b). Two chains (even/odd n) rotated by 2*xv. d: 0=cos, 1=sin.
__device__ __forceinline__ void gen_run(float* v, int a, int b, float xv, float k0f, int d) {
    float c2, s2;
    __sincosf(xv + xv, &s2, &c2);
    float sA, cA, sB, cB;
    __sincosf(xv * k0f,          &sA, &cA);     // fp32 x*k matches reference rounding
    __sincosf(xv * (k0f + 1.f),  &sB, &cB);
    #pragma unroll
    for (int n = 0; n < 16; n++) {
        if (a + n >= b) break;
        if ((n & 1) == 0) {
            v[a + n] = d ? sA : cA;
        } else {
            v[a + n] = d ? sB : cB;
            float ncA = cA * c2 - sA * s2, nsA = sA * c2 + cA * s2;
            float ncB = cB * c2 - sB * s2, nsB = sB * c2 + cB * s2;
            cA = ncA; sA = nsA; cB = ncB; sB = nsB;
        }
    }
}

// 512 producer threads: thread (r, sub) generates the 16 features at
// positions p = chunk*64 + sub*16 + {0..15} for m-row r.
__device__ __forceinline__ void produce(int u, int c0, uint32_t sb, char* smem,
                                        const float* xrow, int t, int r, int sub)
{
    const int slot = u % 3;
    const uint32_t mF = sb + (uint32_t)slot * 8u;
    const int chunk = c0 + u;

    if (t == 0) {   // B: one 32KB pre-swizzled bulk copy
        const char* src = (const char*)g_B + (size_t)chunk * 32768;
        MBAR_EXPECT_TX(mF, (uint32_t)B_SZ);
        asm volatile("cp.async.bulk.shared::cluster.global.mbarrier::complete_tx::bytes "
                     "[%0], [%1], %2, [%3];"
                     :: "r"(sb + CTRL + slot * STG + A_SZ), "l"(src),
                        "r"((uint32_t)B_SZ), "r"(mF) : "memory");
    }

    const int pp0 = chunk * 64 + sub * 16;
    float v[16];

    // runs within these 16 positions (at most one (i,d)-boundary since 300 > 16)
    const int i0 = pp0 / 600;
    const int r60 = pp0 - i0 * 600;
    const int d0 = (r60 >= KG) ? 1 : 0;
    const int k0 = r60 - d0 * KG;                 // 0-based
    int bsplit = KG - k0;                         // positions until k wraps
    if (bsplit >= 16) {
        gen_run(v, 0, 16, xrow[i0], (float)(k0 + 1), d0);
    } else {
        gen_run(v, 0, bsplit, xrow[i0], (float)(k0 + 1), d0);
        const int pB = pp0 + bsplit;              // pB % 300 == 0 -> k starts at 1
        const int iB = pB / 600;
        const int dB = ((pB - iB * 600) >= KG) ? 1 : 0;
        gen_run(v, bsplit, 16, xrow[iB], 1.f, dB);
    }

    uint32_t hv[8];
    #pragma unroll
    for (int p = 0; p < 8; p++) hv[p] = pack_h2(v[2 * p], v[2 * p + 1]);

    char* Arow = smem + CTRL + slot * STG + r * 128;
    const uint32_t msk = (uint32_t)(r & 7);
    const uint32_t ch = (uint32_t)(sub * 2);
    *(uint4*)(Arow + (((ch)     ^ msk) << 4)) = make_uint4(hv[0], hv[1], hv[2], hv[3]);
    *(uint4*)(Arow + (((ch + 1) ^ msk) << 4)) = make_uint4(hv[4], hv[5], hv[6], hv[7]);
    MBAR_ARRIVE(mF);   // release: A stores visible to full-waiters
}

__global__ void __launch_bounds__(NT, 1)
fkan_gemm(const float* __restrict__ x, float* __restrict__ out)
{
    extern __shared__ char smem[];
    const uint32_t sb = s2u(smem);
    const int t = threadIdx.x, lane = t & 31, wid = t >> 5;
    const int b0 = blockIdx.x * BMT;
    const int c0 = (NCHUNK * (int)blockIdx.y) / SPLITS;
    const int c1 = (NCHUNK * ((int)blockIdx.y + 1)) / SPLITS;
    const int ns = c1 - c0;                       // 266 or 267 stages

    if (t == 0) { MBAR_INIT(sb, NT + 1); MBAR_INIT(sb + 8, NT + 1); MBAR_INIT(sb + 16, NT + 1); }
    __syncthreads();

    // producer ids
    const int r = t & 127, sub = t >> 7;
    const float* xrow = x + (size_t)(b0 + r) * ID;

    // consumer: 16 warps as 4(m) x 4(n), warp tile 32x64
    const int wm = wid >> 2, wn = wid & 3;
    const int mbase = wm * 32, nbase = wn * 64;
    const uint32_t msk = (uint32_t)(lane & 7);
    const int a_rl = ((lane >> 3) & 1) * 8 + (lane & 7);
    const uint32_t akh = (uint32_t)(lane >> 4);
    const int b_rl = ((lane >> 4) << 3) + (lane & 7);
    const uint32_t bkh = (uint32_t)((lane >> 3) & 1);
    uint32_t aoff[2], boff[4];
    #pragma unroll
    for (int mi = 0; mi < 2; mi++) aoff[mi] = (uint32_t)(mbase + mi * 16 + a_rl) * 128u;
    #pragma unroll
    for (int g = 0; g < 4; g++)   boff[g] = (uint32_t)(nbase + g * 16 + b_rl) * 128u;

    float acc[2][8][4];
    #pragma unroll
    for (int a = 0; a < 2; a++)
        #pragma unroll
        for (int b = 0; b < 8; b++)
            #pragma unroll
            for (int c = 0; c < 4; c++) acc[a][b][c] = 0.f;

    produce(0, c0, sb, smem, xrow, t, r, sub);
    produce(1, c0, sb, smem, xrow, t, r, sub);
    produce(2, c0, sb, smem, xrow, t, r, sub);

    for (int s = 0; s < ns; s++) {
        const int slot = s % 3;
        const uint32_t ph = (uint32_t)((s / 3) & 1);
        MBAR_WAIT(sb + (uint32_t)slot * 8u, ph);
        const uint32_t Ab = sb + CTRL + slot * STG;
        const uint32_t Bb = Ab + A_SZ;
        #pragma unroll
        for (int kq = 0; kq < 4; kq++) {          // 16 fp16 k per step
            uint32_t av[2][4], bv[4][4];
            const uint32_t ak = ((((uint32_t)(kq * 2) + akh) ^ msk) << 4);
            const uint32_t bk = ((((uint32_t)(kq * 2) + bkh) ^ msk) << 4);
            #pragma unroll
            for (int mi = 0; mi < 2; mi++) LDSM4(av[mi], Ab + aoff[mi] + ak);
            #pragma unroll
            for (int g = 0; g < 4; g++)   LDSM4(bv[g], Bb + boff[g] + bk);
            #pragma unroll
            for (int mi = 0; mi < 2; mi++)
                #pragma unroll
                for (int nt = 0; nt < 8; nt++)
                    mma16(acc[mi][nt], av[mi], &bv[nt >> 1][(nt & 1) * 2]);
        }
        if (s + 3 < ns) {
            __syncthreads();                      // all readers done with this slot
            produce(s + 3, c0, sb, smem, xrow, t, r, sub);
        }
    }

    // epilogue: split-K accumulate (out pre-initialized with bias)
    const int g4 = lane >> 2, t4 = lane & 3;
    #pragma unroll
    for (int mi = 0; mi < 2; mi++) {
        const int row = b0 + mbase + mi * 16 + g4;
        #pragma unroll
        for (int nt = 0; nt < 8; nt++) {
            const int col = nbase + nt * 8 + t4 * 2;
            atomicAdd(out + (size_t)row * JD + col,           acc[mi][nt][0]);
            atomicAdd(out + (size_t)row * JD + col + 1,       acc[mi][nt][1]);
            atomicAdd(out + (size_t)(row + 8) * JD + col,     acc[mi][nt][2]);
            atomicAdd(out + (size_t)(row + 8) * JD + col + 1, acc[mi][nt][3]);
        }
    }
}

// ---------------------------------------------------------------------------
extern "C" void kernel_launch(void* const* d_in, const int* in_sizes, int n_in,
                              void* d_out, int out_size)
{
    const float* x    = (const float*)d_in[0];   // [2048, 256]
    const float* co   = (const float*)d_in[1];   // [2, 256, 256, 300]
    const float* bias = (const float*)d_in[2];   // [1, 256]
    float* out = (float*)d_out;                  // [2048, 256] fp32

    cudaFuncSetAttribute(fkan_gemm, cudaFuncAttributeMaxDynamicSharedMemorySize, SMEM_TOTAL);

    fkan_init<<<(out_size + PTN - 1) / PTN, PTN>>>(out, bias, out_size);
    fkan_pre<<<(int)(((size_t)NCHUNK * JD * 8 + PTN - 1) / PTN), PTN>>>(co);

    dim3 grid(2048 / BMT, SPLITS);               // (16, 9) = 144 CTAs, one wave
    fkan_gemm<<<grid, NT, SMEM_TOTAL>>>(x, out);
}

// round 15
// speedup vs baseline: 1.8388x; 1.8388x over previous
#include <cuda_runtime.h>
#include <cuda_fp16.h>
#include <cstdint>

// NaiveFourierKANLayer via mma.sync fp16 m16n8k16 (sm_103 portable HMMA path).
// y[b,j] = sum_{i,k} cos(x[b,i]k)C0[j,i,k] + sin(x[b,i]k)C1[j,i,k] + bias[j]
// GEMM: M=2048(b), N=256(j), K=(i,plane,k)=153600 (k padded 300->320).
// R15 = R13 (best, 614us) + uneven 9-way i-aligned split-K: grid (16,9)=144
// CTAs fills more of the 148 SMs; max 290 stages/CTA vs 320. produce() stays
// branch-free/statically-indexed (R14's dynamic-indexed variant spilled).

#define NT     512          // gemm threads (16 warps, 4/SMSP)
#define PTN    256          // helper-kernel threads
#define BMT    128          // CTA M tile
#define ID     256
#define JD     256
#define KG     300
#define SPLITS 9            // uneven i-ranges: 28 or 29 i's per CTA
#define KCPI   10           // 32-angle chunks per i (10*32 = 320)

#define CTRL   1024
#define A_SZ   16384        // 128 rows x 128B  ([cos32|sin32] fp16)
#define B_SZ   32768        // 256 rows x 128B  ([C0 k32 | C1 k32] fp16)
#define STG    (A_SZ + B_SZ)
#define SMEM_TOTAL (CTRL + 3 * STG)   // 148480

// fp16, SW128-pre-swizzled coeff tiles, k padded to 320:
// tile (i*10+kc): [256 j rows][8 chunks 16B=8 fp16], chunk c<4 = C0, c>=4 = C1.
__device__ __align__(128) uint32_t g_B[(size_t)ID * KCPI * JD * 32];   // 84 MB

__device__ __forceinline__ uint32_t s2u(const void* p) {
    uint32_t a;
    asm("{ .reg .u64 t; cvta.to.shared.u64 t, %1; cvt.u32.u64 %0, t; }" : "=r"(a) : "l"(p));
    return a;
}
// pack two fp32 -> fp16x2 (lo = first arg, hi = second arg), round-to-nearest
__device__ __forceinline__ uint32_t pack_h2(float lo, float hi) {
    uint32_t r;
    asm("cvt.rn.f16x2.f32 %0, %1, %2;" : "=r"(r) : "f"(hi), "f"(lo));
    return r;
}

#define MBAR_INIT(a, c) asm volatile("mbarrier.init.shared.b64 [%0], %1;" :: "r"(a), "r"(c) : "memory")
#define MBAR_ARRIVE(a)  asm volatile("mbarrier.arrive.shared.b64 _, [%0];" :: "r"(a) : "memory")
#define MBAR_EXPECT_TX(a, b) \
    asm volatile("mbarrier.arrive.expect_tx.shared.b64 _, [%0], %1;" :: "r"(a), "r"(b) : "memory")
#define MBAR_WAIT(a, ph)                                                              \
    asm volatile("{\n\t.reg .pred P;\n\t"                                             \
        "WL_%=:\n\t"                                                                  \
        "mbarrier.try_wait.parity.acquire.cta.shared::cta.b64 P, [%0], %1, 0x989680;\n\t" \
        "@P bra.uni WD_%=;\n\t"                                                       \
        "bra.uni WL_%=;\n\t"                                                          \
        "WD_%=:\n\t}" :: "r"(a), "r"(ph) : "memory")

#define LDSM4(R, addr)                                                                \
    asm volatile("ldmatrix.sync.aligned.m8n8.x4.shared.b16 {%0,%1,%2,%3}, [%4];"      \
        : "=r"((R)[0]), "=r"((R)[1]), "=r"((R)[2]), "=r"((R)[3]) : "r"(addr))

__device__ __forceinline__ void mma16(float* d, const uint32_t* a, const uint32_t* b) {
    asm volatile("mma.sync.aligned.m16n8k16.row.col.f32.f16.f16.f32 "
        "{%0,%1,%2,%3}, {%4,%5,%6,%7}, {%8,%9}, {%0,%1,%2,%3};"
        : "+f"(d[0]), "+f"(d[1]), "+f"(d[2]), "+f"(d[3])
        : "r"(a[0]), "r"(a[1]), "r"(a[2]), "r"(a[3]), "r"(b[0]), "r"(b[1]));
}

// ---------------------------------------------------------------------------
__global__ void __launch_bounds__(PTN)
fkan_init(float* __restrict__ out, const float* __restrict__ bias, int n) {
    int t = blockIdx.x * blockDim.x + threadIdx.x;
    if (t < n) out[t] = bias[t & (JD - 1)];
}

// coeffs[d][j][i][k] -> g_B fp16 tiles, SW128-swizzled, k padded to 320.
// One thread per 16B chunk (8 fp16).
__global__ void __launch_bounds__(PTN)
fkan_pre(const float* __restrict__ co) {
    size_t lin = (size_t)blockIdx.x * PTN + threadIdx.x;   // ((i*10+kc)*256+j)*8+c
    if (lin >= (size_t)ID * KCPI * JD * 8) return;
    int c    = (int)(lin & 7);
    int j    = (int)((lin >> 3) & 255);
    int tile = (int)(lin >> 11);
    int kc   = tile % KCPI;
    int i    = tile / KCPI;
    int d    = c >> 2;
    int k0   = kc * 32 + (c & 3) * 8;

    const float* src = co + ((size_t)(d * JD + j) * ID + i) * KG;
    uint32_t hv[4];
    #pragma unroll
    for (int p = 0; p < 4; p++) {
        int ka = k0 + 2 * p, kb = ka + 1;
        float va = (ka < KG) ? src[ka] : 0.f;
        float vb = (kb < KG) ? src[kb] : 0.f;
        hv[p] = pack_h2(va, vb);                 // low half = ka
    }
    uint32_t off = (uint32_t)j * 32 + (((uint32_t)c ^ (uint32_t)(j & 7)) << 2); // uint32 units
    uint4 w = make_uint4(hv[0], hv[1], hv[2], hv[3]);
    *(uint4*)(g_B + (size_t)tile * 8192 + off) = w;
}

// ---------------------------------------------------------------------------
struct PState { float xv, c2, s2; };

// 512 producer threads: thread (r, h, qq) writes chunks h*4+qq*2, +1
// (16 fp16 angles k = kc*32 + qq*16 + {1..16}) of plane h for m-row r.
__device__ __forceinline__ void produce(int u, uint32_t sb, char* smem, int ibase,
                                        const float* xp, int t, int r, int h, int qq,
                                        PState& P)
{
    const int slot = u % 3;
    const int kc   = u % KCPI;
    const int il   = u / KCPI;
    const uint32_t mF = sb + (uint32_t)slot * 8u;

    if (t == 0) {   // B: one 32KB pre-swizzled bulk copy
        const char* src = (const char*)g_B + (size_t)((ibase + il) * KCPI + kc) * 32768;
        MBAR_EXPECT_TX(mF, (uint32_t)B_SZ);
        asm volatile("cp.async.bulk.shared::cluster.global.mbarrier::complete_tx::bytes "
                     "[%0], [%1], %2, [%3];"
                     :: "r"(sb + CTRL + slot * STG + A_SZ), "l"(src),
                        "r"((uint32_t)B_SZ), "r"(mF) : "memory");
    }

    if (kc == 0) { P.xv = xp[il]; __sincosf(P.xv + P.xv, &P.s2, &P.c2); }

    // 16 angles: seeds at k0, k0+1 (fp32 x*k matches reference rounding),
    // both chains rotated by 2x per step.
    const float k0f = (float)(kc * 32 + qq * 16 + 1);
    float s0, c0, s1, c1;
    __sincosf(P.xv * k0f,         &s0, &c0);
    __sincosf(P.xv * (k0f + 1.f), &s1, &c1);

    const int valid = 299 - kc * 32 - qq * 16;   // angle index a kept iff a <= valid
    uint32_t hv[8];
    #pragma unroll
    for (int p = 0; p < 8; p++) {
        float v0 = h ? s0 : c0;                  // a = 2p
        float v1 = h ? s1 : c1;                  // a = 2p+1
        if (2 * p     > valid) v0 = 0.f;
        if (2 * p + 1 > valid) v1 = 0.f;
        hv[p] = pack_h2(v0, v1);
        if (p < 7) {
            float nc0 = c0 * P.c2 - s0 * P.s2, ns0 = s0 * P.c2 + c0 * P.s2;
            float nc1 = c1 * P.c2 - s1 * P.s2, ns1 = s1 * P.c2 + c1 * P.s2;
            c0 = nc0; s0 = ns0; c1 = nc1; s1 = ns1;
        }
    }

    char* Arow = smem + CTRL + slot * STG + r * 128;
    const uint32_t msk = (uint32_t)(r & 7);
    const uint32_t ch = (uint32_t)(h * 4 + qq * 2);
    *(uint4*)(Arow + (((ch)     ^ msk) << 4)) = make_uint4(hv[0], hv[1], hv[2], hv[3]);
    *(uint4*)(Arow + (((ch + 1) ^ msk) << 4)) = make_uint4(hv[4], hv[5], hv[6], hv[7]);
    MBAR_ARRIVE(mF);   // release: A stores visible to full-waiters
}

__global__ void __launch_bounds__(NT, 1)
fkan_gemm(const float* __restrict__ x, float* __restrict__ out)
{
    extern __shared__ char smem[];
    const uint32_t sb = s2u(smem);
    const int t = threadIdx.x, lane = t & 31, wid = t >> 5;
    const int b0 = blockIdx.x * BMT;
    // uneven i-aligned split-K: this CTA covers i in [ibase, iend)
    const int ibase = (ID * (int)blockIdx.y) / SPLITS;
    const int iend  = (ID * ((int)blockIdx.y + 1)) / SPLITS;
    const int ns    = (iend - ibase) * KCPI;     // 280 or 290 stages

    if (t == 0) { MBAR_INIT(sb, NT + 1); MBAR_INIT(sb + 8, NT + 1); MBAR_INIT(sb + 16, NT + 1); }
    __syncthreads();

    // producer ids
    const int r = t & 127, h = (t >> 7) & 1, qq = t >> 8;
    const float* xp = x + (size_t)(b0 + r) * ID + ibase;
    PState P;

    // consumer: 16 warps as 4(m) x 4(n), warp tile 32x64
    const int wm = wid >> 2, wn = wid & 3;
    const int mbase = wm * 32, nbase = wn * 64;
    const uint32_t msk = (uint32_t)(lane & 7);
    const int a_rl = ((lane >> 3) & 1) * 8 + (lane & 7);   // A: lanes 0-15 rows, 16-31 repeat
    const uint32_t akh = (uint32_t)(lane >> 4);            // A k-half chunk
    const int b_rl = ((lane >> 4) << 3) + (lane & 7);      // B: n-row within group
    const uint32_t bkh = (uint32_t)((lane >> 3) & 1);      // B k-half chunk
    uint32_t aoff[2], boff[4];
    #pragma unroll
    for (int mi = 0; mi < 2; mi++) aoff[mi] = (uint32_t)(mbase + mi * 16 + a_rl) * 128u;
    #pragma unroll
    for (int g = 0; g < 4; g++)   boff[g] = (uint32_t)(nbase + g * 16 + b_rl) * 128u;

    float acc[2][8][4];
    #pragma unroll
    for (int a = 0; a < 2; a++)
        #pragma unroll
        for (int b = 0; b < 8; b++)
            #pragma unroll
            for (int c = 0; c < 4; c++) acc[a][b][c] = 0.f;

    produce(0, sb, smem, ibase, xp, t, r, h, qq, P);
    produce(1, sb, smem, ibase, xp, t, r, h, qq, P);
    produce(2, sb, smem, ibase, xp, t, r, h, qq, P);

    for (int s = 0; s < ns; s++) {
        const int slot = s % 3;
        const uint32_t ph = (uint32_t)((s / 3) & 1);
        MBAR_WAIT(sb + (uint32_t)slot * 8u, ph);
        const uint32_t Ab = sb + CTRL + slot * STG;
        const uint32_t Bb = Ab + A_SZ;
        #pragma unroll
        for (int kq = 0; kq < 4; kq++) {          // 16 fp16 k per step
            uint32_t av[2][4], bv[4][4];
            const uint32_t ak = ((((uint32_t)(kq * 2) + akh) ^ msk) << 4);
            const uint32_t bk = ((((uint32_t)(kq * 2) + bkh) ^ msk) << 4);
            #pragma unroll
            for (int mi = 0; mi < 2; mi++) LDSM4(av[mi], Ab + aoff[mi] + ak);
            #pragma unroll
            for (int g = 0; g < 4; g++)   LDSM4(bv[g], Bb + boff[g] + bk);
            #pragma unroll
            for (int mi = 0; mi < 2; mi++)
                #pragma unroll
                for (int nt = 0; nt < 8; nt++)
                    mma16(acc[mi][nt], av[mi], &bv[nt >> 1][(nt & 1) * 2]);
        }
        if (s + 3 < ns) {
            __syncthreads();                      // all readers done with this slot
            produce(s + 3, sb, smem, ibase, xp, t, r, h, qq, P);
        }
    }

    // epilogue: split-K accumulate (out pre-initialized with bias)
    const int g4 = lane >> 2, t4 = lane & 3;
    #pragma unroll
    for (int mi = 0; mi < 2; mi++) {
        const int row = b0 + mbase + mi * 16 + g4;
        #pragma unroll
        for (int nt = 0; nt < 8; nt++) {
            const int col = nbase + nt * 8 + t4 * 2;
            atomicAdd(out + (size_t)row * JD + col,           acc[mi][nt][0]);
            atomicAdd(out + (size_t)row * JD + col + 1,       acc[mi][nt][1]);
            atomicAdd(out + (size_t)(row + 8) * JD + col,     acc[mi][nt][2]);
            atomicAdd(out + (size_t)(row + 8) * JD + col + 1, acc[mi][nt][3]);
        }
    }
}

// ---------------------------------------------------------------------------
extern "C" void kernel_launch(void* const* d_in, const int* in_sizes, int n_in,
                              void* d_out, int out_size)
{
    const float* x    = (const float*)d_in[0];   // [2048, 256]
    const float* co   = (const float*)d_in[1];   // [2, 256, 256, 300]
    const float* bias = (const float*)d_in[2];   // [1, 256]
    float* out = (float*)d_out;                  // [2048, 256] fp32

    cudaFuncSetAttribute(fkan_gemm, cudaFuncAttributeMaxDynamicSharedMemorySize, SMEM_TOTAL);

    fkan_init<<<(out_size + PTN - 1) / PTN, PTN>>>(out, bias, out_size);
    fkan_pre<<<(int)(((size_t)ID * KCPI * JD * 8 + PTN - 1) / PTN), PTN>>>(co);

    dim3 grid(2048 / BMT, SPLITS);               // (16, 9) = 144 CTAs, one wave
    fkan_gemm<<<grid, NT, SMEM_TOTAL>>>(x, out);
}

// round 16
// speedup vs baseline: 2.0472x; 1.1133x over previous
#include <cuda_runtime.h>
#include <cuda_fp16.h>
#include <cstdint>

// NaiveFourierKANLayer via mma.sync fp16 m16n8k16 (sm_103 portable HMMA path).
// y[b,j] = sum_{i,k} cos(x[b,i]k)C0[j,i,k] + sin(x[b,i]k)C1[j,i,k] + bias[j]
// GEMM: M=2048(b), N=256(j). K flattened into 16-position units
// u = (i, plane, c16), c16 in [0,19) (k padded 300->304 per plane, 1.3% waste).
// 9728 units = 2432 stages of K=64 (4 units/stage). Split-K: 9 stage-ranges
// -> grid (16,9)=144 CTAs, max 271 stages (was 290 with per-i padding to 320).

#define NT     512          // gemm threads (16 warps, 4/SMSP)
#define PTN    256          // helper-kernel threads
#define BMT    128          // CTA M tile
#define ID     256
#define JD     256
#define KG     300
#define SPLITS 9
#define UPI    38           // units per i: 2 planes x 19
#define C16PP  19           // 16-chunks per plane (19*16 = 304)
#define NSTG   2432         // (256*38)/4 total stages

#define CTRL   1024
#define A_SZ   16384        // 128 rows x 128B (64 fp16 features per row)
#define B_SZ   32768        // 256 rows x 128B (64 fp16 coeffs per row)
#define STG    (A_SZ + B_SZ)
#define SMEM_TOTAL (CTRL + 3 * STG)   // 148480

// fp16, SW128-pre-swizzled coeff tiles: tile T (=stage) holds units
// u = T*4+sub at row chunks {2sub, 2sub+1}; [256 j rows][8 chunks 16B].
__device__ __align__(128) uint32_t g_B[(size_t)NSTG * JD * 32];   // 79.7 MB

__device__ __forceinline__ uint32_t s2u(const void* p) {
    uint32_t a;
    asm("{ .reg .u64 t; cvta.to.shared.u64 t, %1; cvt.u32.u64 %0, t; }" : "=r"(a) : "l"(p));
    return a;
}
// pack two fp32 -> fp16x2 (lo = first arg, hi = second arg), round-to-nearest
__device__ __forceinline__ uint32_t pack_h2(float lo, float hi) {
    uint32_t r;
    asm("cvt.rn.f16x2.f32 %0, %1, %2;" : "=r"(r) : "f"(hi), "f"(lo));
    return r;
}

#define MBAR_INIT(a, c) asm volatile("mbarrier.init.shared.b64 [%0], %1;" :: "r"(a), "r"(c) : "memory")
#define MBAR_ARRIVE(a)  asm volatile("mbarrier.arrive.shared.b64 _, [%0];" :: "r"(a) : "memory")
#define MBAR_EXPECT_TX(a, b) \
    asm volatile("mbarrier.arrive.expect_tx.shared.b64 _, [%0], %1;" :: "r"(a), "r"(b) : "memory")
#define MBAR_WAIT(a, ph)                                                              \
    asm volatile("{\n\t.reg .pred P;\n\t"                                             \
        "WL_%=:\n\t"                                                                  \
        "mbarrier.try_wait.parity.acquire.cta.shared::cta.b64 P, [%0], %1, 0x989680;\n\t" \
        "@P bra.uni WD_%=;\n\t"                                                       \
        "bra.uni WL_%=;\n\t"                                                          \
        "WD_%=:\n\t}" :: "r"(a), "r"(ph) : "memory")

#define LDSM4(R, addr)                                                                \
    asm volatile("ldmatrix.sync.aligned.m8n8.x4.shared.b16 {%0,%1,%2,%3}, [%4];"      \
        : "=r"((R)[0]), "=r"((R)[1]), "=r"((R)[2]), "=r"((R)[3]) : "r"(addr))

__device__ __forceinline__ void mma16(float* d, const uint32_t* a, const uint32_t* b) {
    asm volatile("mma.sync.aligned.m16n8k16.row.col.f32.f16.f16.f32 "
        "{%0,%1,%2,%3}, {%4,%5,%6,%7}, {%8,%9}, {%0,%1,%2,%3};"
        : "+f"(d[0]), "+f"(d[1]), "+f"(d[2]), "+f"(d[3])
        : "r"(a[0]), "r"(a[1]), "r"(a[2]), "r"(a[3]), "r"(b[0]), "r"(b[1]));
}

// ---------------------------------------------------------------------------
__global__ void __launch_bounds__(PTN)
fkan_init(float* __restrict__ out, const float* __restrict__ bias, int n) {
    int t = blockIdx.x * blockDim.x + threadIdx.x;
    if (t < n) out[t] = bias[t & (JD - 1)];
}

// coeffs[d][j][i][k] -> g_B fp16 tiles via the unit map, SW128-swizzled.
// One thread per 16B chunk (8 fp16 = half a unit).
__global__ void __launch_bounds__(PTN)
fkan_pre(const float* __restrict__ co) {
    size_t lin = (size_t)blockIdx.x * PTN + threadIdx.x;   // (T*256+j)*8+c
    if (lin >= (size_t)NSTG * JD * 8) return;
    int c = (int)(lin & 7);
    int j = (int)((lin >> 3) & 255);
    int T = (int)(lin >> 11);

    int u    = T * 4 + (c >> 1);
    int i    = u / UPI;
    int rem  = u - i * UPI;
    int pl   = rem / C16PP;
    int c16  = rem - pl * C16PP;
    int k0   = c16 * 16 + (c & 1) * 8;           // 0-based k of first element

    const float* src = co + ((size_t)(pl * JD + j) * ID + i) * KG;
    uint32_t hv[4];
    #pragma unroll
    for (int p = 0; p < 4; p++) {
        int ka = k0 + 2 * p, kb = ka + 1;
        float va = (ka < KG) ? src[ka] : 0.f;
        float vb = (kb < KG) ? src[kb] : 0.f;
        hv[p] = pack_h2(va, vb);                 // low half = ka
    }
    uint32_t off = (uint32_t)j * 32 + (((uint32_t)c ^ (uint32_t)(j & 7)) << 2); // u32 units
    *(uint4*)(g_B + (size_t)T * 8192 + off) = make_uint4(hv[0], hv[1], hv[2], hv[3]);
}

// ---------------------------------------------------------------------------
// 512 producer threads: thread (r, sub) generates unit u = stage*4+sub
// (16 fp16 angles, one (i, plane), k = c16*16 + {1..16}) for m-row r.
__device__ __forceinline__ void produce(int gstage, int slot, uint32_t sb, char* smem,
                                        const float* xrow, int t, int r, int sub)
{
    const uint32_t mF = sb + (uint32_t)slot * 8u;

    if (t == 0) {   // B: one 32KB pre-swizzled bulk copy
        const char* src = (const char*)g_B + (size_t)gstage * 32768;
        MBAR_EXPECT_TX(mF, (uint32_t)B_SZ);
        asm volatile("cp.async.bulk.shared::cluster.global.mbarrier::complete_tx::bytes "
                     "[%0], [%1], %2, [%3];"
                     :: "r"(sb + CTRL + slot * STG + A_SZ), "l"(src),
                        "r"((uint32_t)B_SZ), "r"(mF) : "memory");
    }

    // unit decode (branch-free; const-div -> mul/shift)
    const int u   = gstage * 4 + sub;
    const int i   = u / UPI;
    const int rem = u - i * UPI;
    const int pl  = rem / C16PP;                  // 0=cos, 1=sin
    const int c16 = rem - pl * C16PP;

    const float xv = __ldg(xrow + i);
    float c2, s2;
    __sincosf(xv + xv, &s2, &c2);                 // rotation by 2x

    // seeds at k0, k0+1 (fp32 x*k matches reference rounding)
    const float k0f = (float)(c16 * 16 + 1);
    float s0, c0, s1, c1;
    __sincosf(xv * k0f,         &s0, &c0);
    __sincosf(xv * (k0f + 1.f), &s1, &c1);

    const int valid = 299 - c16 * 16;             // angle idx a kept iff a <= valid
    uint32_t hv[8];
    #pragma unroll
    for (int p = 0; p < 8; p++) {
        float v0 = pl ? s0 : c0;                  // a = 2p
        float v1 = pl ? s1 : c1;                  // a = 2p+1
        if (2 * p     > valid) v0 = 0.f;
        if (2 * p + 1 > valid) v1 = 0.f;
        hv[p] = pack_h2(v0, v1);
        if (p < 7) {
            float nc0 = c0 * c2 - s0 * s2, ns0 = s0 * c2 + c0 * s2;
            float nc1 = c1 * c2 - s1 * s2, ns1 = s1 * c2 + c1 * s2;
            c0 = nc0; s0 = ns0; c1 = nc1; s1 = ns1;
        }
    }

    char* Arow = smem + CTRL + slot * STG + r * 128;
    const uint32_t msk = (uint32_t)(r & 7);
    const uint32_t ch = (uint32_t)(sub * 2);
    *(uint4*)(Arow + (((ch)     ^ msk) << 4)) = make_uint4(hv[0], hv[1], hv[2], hv[3]);
    *(uint4*)(Arow + (((ch + 1) ^ msk) << 4)) = make_uint4(hv[4], hv[5], hv[6], hv[7]);
    MBAR_ARRIVE(mF);   // release: A stores visible to full-waiters
}

__global__ void __launch_bounds__(NT, 1)
fkan_gemm(const float* __restrict__ x, float* __restrict__ out)
{
    extern __shared__ char smem[];
    const uint32_t sb = s2u(smem);
    const int t = threadIdx.x, lane = t & 31, wid = t >> 5;
    const int b0 = blockIdx.x * BMT;
    // stage-granular split-K
    const int s0g = (NSTG * (int)blockIdx.y) / SPLITS;
    const int s1g = (NSTG * ((int)blockIdx.y + 1)) / SPLITS;
    const int ns  = s1g - s0g;                    // 270 or 271

    if (t == 0) { MBAR_INIT(sb, NT + 1); MBAR_INIT(sb + 8, NT + 1); MBAR_INIT(sb + 16, NT + 1); }
    __syncthreads();

    // producer ids
    const int r = t & 127, sub = t >> 7;
    const float* xrow = x + (size_t)(b0 + r) * ID;

    // consumer: 16 warps as 4(m) x 4(n), warp tile 32x64
    const int wm = wid >> 2, wn = wid & 3;
    const int mbase = wm * 32, nbase = wn * 64;
    const uint32_t msk = (uint32_t)(lane & 7);
    const int a_rl = ((lane >> 3) & 1) * 8 + (lane & 7);
    const uint32_t akh = (uint32_t)(lane >> 4);
    const int b_rl = ((lane >> 4) << 3) + (lane & 7);
    const uint32_t bkh = (uint32_t)((lane >> 3) & 1);
    uint32_t aoff[2], boff[4];
    #pragma unroll
    for (int mi = 0; mi < 2; mi++) aoff[mi] = (uint32_t)(mbase + mi * 16 + a_rl) * 128u;
    #pragma unroll
    for (int g = 0; g < 4; g++)   boff[g] = (uint32_t)(nbase + g * 16 + b_rl) * 128u;

    float acc[2][8][4];
    #pragma unroll
    for (int a = 0; a < 2; a++)
        #pragma unroll
        for (int b = 0; b < 8; b++)
            #pragma unroll
            for (int c = 0; c < 4; c++) acc[a][b][c] = 0.f;

    produce(s0g + 0, 0, sb, smem, xrow, t, r, sub);
    produce(s0g + 1, 1, sb, smem, xrow, t, r, sub);
    produce(s0g + 2, 2, sb, smem, xrow, t, r, sub);

    for (int s = 0; s < ns; s++) {
        const int slot = s % 3;
        const uint32_t ph = (uint32_t)((s / 3) & 1);
        MBAR_WAIT(sb + (uint32_t)slot * 8u, ph);
        const uint32_t Ab = sb + CTRL + slot * STG;
        const uint32_t Bb = Ab + A_SZ;
        #pragma unroll
        for (int kq = 0; kq < 4; kq++) {          // 16 fp16 k per step
            uint32_t av[2][4], bv[4][4];
            const uint32_t ak = ((((uint32_t)(kq * 2) + akh) ^ msk) << 4);
            const uint32_t bk = ((((uint32_t)(kq * 2) + bkh) ^ msk) << 4);
            #pragma unroll
            for (int mi = 0; mi < 2; mi++) LDSM4(av[mi], Ab + aoff[mi] + ak);
            #pragma unroll
            for (int g = 0; g < 4; g++)   LDSM4(bv[g], Bb + boff[g] + bk);
            #pragma unroll
            for (int mi = 0; mi < 2; mi++)
                #pragma unroll
                for (int nt = 0; nt < 8; nt++)
                    mma16(acc[mi][nt], av[mi], &bv[nt >> 1][(nt & 1) * 2]);
        }
        if (s + 3 < ns) {
            __syncthreads();                      // all readers done with this slot
            produce(s0g + s + 3, slot, sb, smem, xrow, t, r, sub);
        }
    }

    // epilogue: split-K accumulate (out pre-initialized with bias)
    const int g4 = lane >> 2, t4 = lane & 3;
    #pragma unroll
    for (int mi = 0; mi < 2; mi++) {
        const int row = b0 + mbase + mi * 16 + g4;
        #pragma unroll
        for (int nt = 0; nt < 8; nt++) {
            const int col = nbase + nt * 8 + t4 * 2;
            atomicAdd(out + (size_t)row * JD + col,           acc[mi][nt][0]);
            atomicAdd(out + (size_t)row * JD + col + 1,       acc[mi][nt][1]);
            atomicAdd(out + (size_t)(row + 8) * JD + col,     acc[mi][nt][2]);
            atomicAdd(out + (size_t)(row + 8) * JD + col + 1, acc[mi][nt][3]);
        }
    }
}

// ---------------------------------------------------------------------------
extern "C" void kernel_launch(void* const* d_in, const int* in_sizes, int n_in,
                              void* d_out, int out_size)
{
    const float* x    = (const float*)d_in[0];   // [2048, 256]
    const float* co   = (const float*)d_in[1];   // [2, 256, 256, 300]
    const float* bias = (const float*)d_in[2];   // [1, 256]
    float* out = (float*)d_out;                  // [2048, 256] fp32

    cudaFuncSetAttribute(fkan_gemm, cudaFuncAttributeMaxDynamicSharedMemorySize, SMEM_TOTAL);

    fkan_init<<<(out_size + PTN - 1) / PTN, PTN>>>(out, bias, out_size);
    fkan_pre<<<(int)(((size_t)NSTG * JD * 8 + PTN - 1) / PTN), PTN>>>(co);

    dim3 grid(2048 / BMT, SPLITS);               // (16, 9) = 144 CTAs, one wave
    fkan_gemm<<<grid, NT, SMEM_TOTAL>>>(x, out);
}

// round 17
// speedup vs baseline: 2.1523x; 1.0513x over previous
#include <cuda_runtime.h>
#include <cuda_fp16.h>
#include <cstdint>

// NaiveFourierKANLayer via mma.sync fp16 m16n8k16 (sm_103 portable HMMA path).
// y[b,j] = sum_{i,k} cos(x[b,i]k)C0[j,i,k] + sin(x[b,i]k)C1[j,i,k] + bias[j]
// GEMM: M=2048(b), N=256(j). K flattened into 16-position units
// u = (i, plane, c16), c16 in [0,19) (k padded 300->304 per plane, 1.3% waste).
// R17: K=128 stages (2 of the old 64-K tiles per stage), ring-2 double buffer;
// halves per-stage fixed cost (mbar/sync/produce re-entry) per MMA.
// 1216 stages; split-K 9 stage-ranges -> grid (16,9)=144 CTAs, max 136 stages.

#define NT     512          // gemm threads (16 warps, 4/SMSP)
#define PTN    256          // helper-kernel threads
#define BMT    128          // CTA M tile
#define ID     256
#define JD     256
#define KG     300
#define SPLITS 9
#define UPI    38           // units per i: 2 planes x 19
#define C16PP  19           // 16-chunks per plane (19*16 = 304)
#define NT64   2432         // total 64-K tiles
#define NSTG   1216         // total K=128 stages

#define CTRL   1024
#define A_HSZ  16384        // one A half: 128 rows x 128B
#define B_HSZ  32768        // one B half: 256 rows x 128B
#define STG    (2 * A_HSZ + 2 * B_HSZ)            // 98304
#define B_OFF  (2 * A_HSZ)
#define SMEM_TOTAL (CTRL + 2 * STG)               // 197632

// fp16, SW128-pre-swizzled coeff tiles: 64-K tile T holds units u=T*4+sub at
// row chunks {2sub,2sub+1}; [256 j rows][8 chunks 16B]. Two consecutive tiles
// are contiguous -> one 64KB bulk per K=128 stage.
__device__ __align__(128) uint32_t g_B[(size_t)NT64 * JD * 32];   // 79.7 MB

__device__ __forceinline__ uint32_t s2u(const void* p) {
    uint32_t a;
    asm("{ .reg .u64 t; cvta.to.shared.u64 t, %1; cvt.u32.u64 %0, t; }" : "=r"(a) : "l"(p));
    return a;
}
// pack two fp32 -> fp16x2 (lo = first arg, hi = second arg), round-to-nearest
__device__ __forceinline__ uint32_t pack_h2(float lo, float hi) {
    uint32_t r;
    asm("cvt.rn.f16x2.f32 %0, %1, %2;" : "=r"(r) : "f"(hi), "f"(lo));
    return r;
}

#define MBAR_INIT(a, c) asm volatile("mbarrier.init.shared.b64 [%0], %1;" :: "r"(a), "r"(c) : "memory")
#define MBAR_ARRIVE(a)  asm volatile("mbarrier.arrive.shared.b64 _, [%0];" :: "r"(a) : "memory")
#define MBAR_EXPECT_TX(a, b) \
    asm volatile("mbarrier.arrive.expect_tx.shared.b64 _, [%0], %1;" :: "r"(a), "r"(b) : "memory")
#define MBAR_WAIT(a, ph)                                                              \
    asm volatile("{\n\t.reg .pred P;\n\t"                                             \
        "WL_%=:\n\t"                                                                  \
        "mbarrier.try_wait.parity.acquire.cta.shared::cta.b64 P, [%0], %1, 0x989680;\n\t" \
        "@P bra.uni WD_%=;\n\t"                                                       \
        "bra.uni WL_%=;\n\t"                                                          \
        "WD_%=:\n\t}" :: "r"(a), "r"(ph) : "memory")

#define LDSM4(R, addr)                                                                \
    asm volatile("ldmatrix.sync.aligned.m8n8.x4.shared.b16 {%0,%1,%2,%3}, [%4];"      \
        : "=r"((R)[0]), "=r"((R)[1]), "=r"((R)[2]), "=r"((R)[3]) : "r"(addr))

__device__ __forceinline__ void mma16(float* d, const uint32_t* a, const uint32_t* b) {
    asm volatile("mma.sync.aligned.m16n8k16.row.col.f32.f16.f16.f32 "
        "{%0,%1,%2,%3}, {%4,%5,%6,%7}, {%8,%9}, {%0,%1,%2,%3};"
        : "+f"(d[0]), "+f"(d[1]), "+f"(d[2]), "+f"(d[3])
        : "r"(a[0]), "r"(a[1]), "r"(a[2]), "r"(a[3]), "r"(b[0]), "r"(b[1]));
}

// ---------------------------------------------------------------------------
__global__ void __launch_bounds__(PTN)
fkan_init(float* __restrict__ out, const float* __restrict__ bias, int n) {
    int t = blockIdx.x * blockDim.x + threadIdx.x;
    if (t < n) out[t] = bias[t & (JD - 1)];
}

// coeffs[d][j][i][k] -> g_B fp16 tiles via the unit map, SW128-swizzled.
// One thread per 16B chunk (8 fp16 = half a unit).
__global__ void __launch_bounds__(PTN)
fkan_pre(const float* __restrict__ co) {
    size_t lin = (size_t)blockIdx.x * PTN + threadIdx.x;   // (T*256+j)*8+c
    if (lin >= (size_t)NT64 * JD * 8) return;
    int c = (int)(lin & 7);
    int j = (int)((lin >> 3) & 255);
    int T = (int)(lin >> 11);

    int u    = T * 4 + (c >> 1);
    int i    = u / UPI;
    int rem  = u - i * UPI;
    int pl   = rem / C16PP;
    int c16  = rem - pl * C16PP;
    int k0   = c16 * 16 + (c & 1) * 8;           // 0-based k of first element

    const float* src = co + ((size_t)(pl * JD + j) * ID + i) * KG;
    uint32_t hv[4];
    #pragma unroll
    for (int p = 0; p < 4; p++) {
        int ka = k0 + 2 * p, kb = ka + 1;
        float va = (ka < KG) ? src[ka] : 0.f;
        float vb = (kb < KG) ? src[kb] : 0.f;
        hv[p] = pack_h2(va, vb);                 // low half = ka
    }
    uint32_t off = (uint32_t)j * 32 + (((uint32_t)c ^ (uint32_t)(j & 7)) << 2); // u32 units
    *(uint4*)(g_B + (size_t)T * 8192 + off) = make_uint4(hv[0], hv[1], hv[2], hv[3]);
}

// ---------------------------------------------------------------------------
// Produce one 64-K half: thread (r, sub) generates unit u = T64*4+sub
// (16 fp16 angles, one (i, plane), k = c16*16 + {1..16}) for m-row r.
// t0 issues the 64KB bulk (both halves) on half 0 only.
__device__ __forceinline__ void produce_half(int T64, int slot, int half,
                                             uint32_t sb, char* smem,
                                             const float* xrow, int t, int r, int sub)
{
    const uint32_t mF = sb + (uint32_t)slot * 8u;

    if (half == 0 && t == 0) {   // B: one 64KB pre-swizzled bulk (two tiles)
        const char* src = (const char*)g_B + (size_t)T64 * 32768;
        MBAR_EXPECT_TX(mF, 65536u);
        asm volatile("cp.async.bulk.shared::cluster.global.mbarrier::complete_tx::bytes "
                     "[%0], [%1], %2, [%3];"
                     :: "r"(sb + CTRL + slot * STG + B_OFF), "l"(src),
                        "r"(65536u), "r"(mF) : "memory");
    }

    // unit decode (branch-free; const-div -> mul/shift)
    const int u   = T64 * 4 + sub;
    const int i   = u / UPI;
    const int rem = u - i * UPI;
    const int pl  = rem / C16PP;                  // 0=cos, 1=sin
    const int c16 = rem - pl * C16PP;

    const float xv = __ldg(xrow + i);
    float c2, s2;
    __sincosf(xv + xv, &s2, &c2);                 // rotation by 2x

    // seeds at k0, k0+1 (fp32 x*k matches reference rounding)
    const float k0f = (float)(c16 * 16 + 1);
    float s0, c0, s1, c1;
    __sincosf(xv * k0f,         &s0, &c0);
    __sincosf(xv * (k0f + 1.f), &s1, &c1);

    const int valid = 299 - c16 * 16;             // angle idx a kept iff a <= valid
    uint32_t hv[8];
    #pragma unroll
    for (int p = 0; p < 8; p++) {
        float v0 = pl ? s0 : c0;                  // a = 2p
        float v1 = pl ? s1 : c1;                  // a = 2p+1
        if (2 * p     > valid) v0 = 0.f;
        if (2 * p + 1 > valid) v1 = 0.f;
        hv[p] = pack_h2(v0, v1);
        if (p < 7) {
            float nc0 = c0 * c2 - s0 * s2, ns0 = s0 * c2 + c0 * s2;
            float nc1 = c1 * c2 - s1 * s2, ns1 = s1 * c2 + c1 * s2;
            c0 = nc0; s0 = ns0; c1 = nc1; s1 = ns1;
        }
    }

    char* Arow = smem + CTRL + slot * STG + half * A_HSZ + r * 128;
    const uint32_t msk = (uint32_t)(r & 7);
    const uint32_t ch = (uint32_t)(sub * 2);
    *(uint4*)(Arow + (((ch)     ^ msk) << 4)) = make_uint4(hv[0], hv[1], hv[2], hv[3]);
    *(uint4*)(Arow + (((ch + 1) ^ msk) << 4)) = make_uint4(hv[4], hv[5], hv[6], hv[7]);
    MBAR_ARRIVE(mF);
}

__device__ __forceinline__ void produce_stage(int stage, int slot, uint32_t sb, char* smem,
                                              const float* xrow, int t, int r, int sub)
{
    produce_half(stage * 2,     slot, 0, sb, smem, xrow, t, r, sub);
    produce_half(stage * 2 + 1, slot, 1, sb, smem, xrow, t, r, sub);
}

__global__ void __launch_bounds__(NT, 1)
fkan_gemm(const float* __restrict__ x, float* __restrict__ out)
{
    extern __shared__ char smem[];
    const uint32_t sb = s2u(smem);
    const int t = threadIdx.x, lane = t & 31, wid = t >> 5;
    const int b0 = blockIdx.x * BMT;
    // stage-granular split-K over K=128 stages
    const int s0g = (NSTG * (int)blockIdx.y) / SPLITS;
    const int s1g = (NSTG * ((int)blockIdx.y + 1)) / SPLITS;
    const int ns  = s1g - s0g;                    // 135 or 136

    // 2x512 producer arrivals + 1 expect_tx arrive = 1025 per stage
    if (t == 0) { MBAR_INIT(sb, 1025); MBAR_INIT(sb + 8, 1025); }
    __syncthreads();

    // producer ids
    const int r = t & 127, sub = t >> 7;
    const float* xrow = x + (size_t)(b0 + r) * ID;

    // consumer: 16 warps as 4(m) x 4(n), warp tile 32x64
    const int wm = wid >> 2, wn = wid & 3;
    const int mbase = wm * 32, nbase = wn * 64;
    const uint32_t msk = (uint32_t)(lane & 7);
    const int a_rl = ((lane >> 3) & 1) * 8 + (lane & 7);
    const uint32_t akh = (uint32_t)(lane >> 4);
    const int b_rl = ((lane >> 4) << 3) + (lane & 7);
    const uint32_t bkh = (uint32_t)((lane >> 3) & 1);
    uint32_t aoff[2], boff[4];
    #pragma unroll
    for (int mi = 0; mi < 2; mi++) aoff[mi] = (uint32_t)(mbase + mi * 16 + a_rl) * 128u;
    #pragma unroll
    for (int g = 0; g < 4; g++)   boff[g] = (uint32_t)(nbase + g * 16 + b_rl) * 128u;

    float acc[2][8][4];
    #pragma unroll
    for (int a = 0; a < 2; a++)
        #pragma unroll
        for (int b = 0; b < 8; b++)
            #pragma unroll
            for (int c = 0; c < 4; c++) acc[a][b][c] = 0.f;

    produce_stage(s0g + 0, 0, sb, smem, xrow, t, r, sub);
    produce_stage(s0g + 1, 1, sb, smem, xrow, t, r, sub);

    for (int s = 0; s < ns; s++) {
        const int slot = s & 1;
        const uint32_t ph = (uint32_t)((s >> 1) & 1);
        MBAR_WAIT(sb + (uint32_t)slot * 8u, ph);
        const uint32_t Sb = sb + CTRL + slot * STG;
        #pragma unroll
        for (int kq = 0; kq < 8; kq++) {          // 16 fp16 k per step, 128 total
            const uint32_t Ab = Sb + (uint32_t)(kq >> 2) * A_HSZ;
            const uint32_t Bb = Sb + B_OFF + (uint32_t)(kq >> 2) * B_HSZ;
            const uint32_t kql = (uint32_t)(kq & 3);
            uint32_t av[2][4], bv[4][4];
            const uint32_t ak = (((kql * 2 + akh) ^ msk) << 4);
            const uint32_t bk = (((kql * 2 + bkh) ^ msk) << 4);
            #pragma unroll
            for (int mi = 0; mi < 2; mi++) LDSM4(av[mi], Ab + aoff[mi] + ak);
            #pragma unroll
            for (int g = 0; g < 4; g++)   LDSM4(bv[g], Bb + boff[g] + bk);
            #pragma unroll
            for (int mi = 0; mi < 2; mi++)
                #pragma unroll
                for (int nt = 0; nt < 8; nt++)
                    mma16(acc[mi][nt], av[mi], &bv[nt >> 1][(nt & 1) * 2]);
        }
        if (s + 2 < ns) {
            __syncthreads();                      // all readers done with this slot
            produce_stage(s0g + s + 2, slot, sb, smem, xrow, t, r, sub);
        }
    }

    // epilogue: split-K accumulate (out pre-initialized with bias)
    const int g4 = lane >> 2, t4 = lane & 3;
    #pragma unroll
    for (int mi = 0; mi < 2; mi++) {
        const int row = b0 + mbase + mi * 16 + g4;
        #pragma unroll
        for (int nt = 0; nt < 8; nt++) {
            const int col = nbase + nt * 8 + t4 * 2;
            atomicAdd(out + (size_t)row * JD + col,           acc[mi][nt][0]);
            atomicAdd(out + (size_t)row * JD + col + 1,       acc[mi][nt][1]);
            atomicAdd(out + (size_t)(row + 8) * JD + col,     acc[mi][nt][2]);
            atomicAdd(out + (size_t)(row + 8) * JD + col + 1, acc[mi][nt][3]);
        }
    }
}

// ---------------------------------------------------------------------------
extern "C" void kernel_launch(void* const* d_in, const int* in_sizes, int n_in,
                              void* d_out, int out_size)
{
    const float* x    = (const float*)d_in[0];   // [2048, 256]
    const float* co   = (const float*)d_in[1];   // [2, 256, 256, 300]
    const float* bias = (const float*)d_in[2];   // [1, 256]
    float* out = (float*)d_out;                  // [2048, 256] fp32

    cudaFuncSetAttribute(fkan_gemm, cudaFuncAttributeMaxDynamicSharedMemorySize, SMEM_TOTAL);

    fkan_init<<<(out_size + PTN - 1) / PTN, PTN>>>(out, bias, out_size);
    fkan_pre<<<(int)(((size_t)NT64 * JD * 8 + PTN - 1) / PTN), PTN>>>(co);

    dim3 grid(2048 / BMT, SPLITS);               // (16, 9) = 144 CTAs, one wave
    fkan_gemm<<<grid, NT, SMEM_TOTAL>>>(x, out);
}